// round 4
// baseline (speedup 1.0000x reference)
#include <cuda_runtime.h>
#include <math.h>

#define NROWS 8192
#define KDIM  512
#define DDIM  256

// ---------------- scratch (no cudaMalloc allowed) ----------------
__device__ float g_Wh[NROWS * DDIM];   // 8 MB
__device__ float g_Wh1[NROWS];
__device__ float g_Wh2[NROWS];

// ---------------- f32x2 packed-FMA helpers (Blackwell) ----------------
__device__ __forceinline__ unsigned long long dup2f(float x) {
    unsigned long long r;
    asm("mov.b64 %0, {%1, %1};" : "=l"(r) : "f"(x));
    return r;
}
__device__ __forceinline__ unsigned long long ffma2(unsigned long long a,
                                                    unsigned long long b,
                                                    unsigned long long c) {
    unsigned long long d;
    asm("fma.rn.f32x2 %0, %1, %2, %3;" : "=l"(d) : "l"(a), "l"(b), "l"(c));
    return d;
}
__device__ __forceinline__ float2 unpack2(unsigned long long v) {
    float x, y;
    asm("mov.b64 {%0, %1}, %2;" : "=f"(x), "=f"(y) : "l"(v));
    return make_float2(x, y);
}

// ---------------- cp.async helpers ----------------
__device__ __forceinline__ void cp16(void* s, const void* g) {
    unsigned sa = (unsigned)__cvta_generic_to_shared(s);
    asm volatile("cp.async.cg.shared.global [%0], [%1], 16;" :: "r"(sa), "l"(g));
}
__device__ __forceinline__ void cp_commit() { asm volatile("cp.async.commit_group;"); }
__device__ __forceinline__ void cp_wait0()  { asm volatile("cp.async.wait_group 0;" ::: "memory"); }

// =====================================================================
// Kernel 1: Wh = input[8192,512] @ weight[512,256]
// 128x128 block tile, 8x8 micro tile, f32x2 accumulators, double-buffered.
// grid (2, 64), 256 threads.
// =====================================================================
__global__ void __launch_bounds__(256) k_gemm_wh(const float* __restrict__ A,
                                                 const float* __restrict__ B) {
    __shared__ __align__(16) float As[2][8][132];   // transposed [k][m], padded
    __shared__ __align__(16) float Bs[2][8][128];

    const int t   = threadIdx.x;
    const int m0g = blockIdx.y * 128;
    const int n0g = blockIdx.x * 128;

    const int arow = t >> 1, ac4 = (t & 1) * 4;     // A tile: 128 rows x 8 cols
    const int brow = t >> 5, bc  = (t & 31) * 4;    // B tile: 8 rows x 128 cols

    // ---- prologue: tile 0 ----
    float4 aReg = *(const float4*)&A[(size_t)(m0g + arow) * KDIM + ac4];
    cp16(&Bs[0][brow][bc], &B[(size_t)brow * DDIM + n0g + bc]);
    cp_commit();
#pragma unroll
    for (int i = 0; i < 4; i++) As[0][ac4 + i][arow] = ((const float*)&aReg)[i];
    cp_wait0();
    __syncthreads();

    unsigned long long acc[8][4];
#pragma unroll
    for (int i = 0; i < 8; i++)
#pragma unroll
        for (int j = 0; j < 4; j++) acc[i][j] = 0ull;

    const int m0 = (t >> 4) * 8, n0 = (t & 15) * 8;

    for (int kt = 0; kt < KDIM / 8; ++kt) {
        const int cur = kt & 1, nxt = cur ^ 1;
        float4 aN;
        if (kt < KDIM / 8 - 1) {
            aN = *(const float4*)&A[(size_t)(m0g + arow) * KDIM + (kt + 1) * 8 + ac4];
            cp16(&Bs[nxt][brow][bc], &B[(size_t)((kt + 1) * 8 + brow) * DDIM + n0g + bc]);
            cp_commit();
        }
#pragma unroll
        for (int kk = 0; kk < 8; kk++) {
            float4 a_lo = *(const float4*)&As[cur][kk][m0];
            float4 a_hi = *(const float4*)&As[cur][kk][m0 + 4];
            ulonglong2 b01 = *(const ulonglong2*)&Bs[cur][kk][n0];
            ulonglong2 b23 = *(const ulonglong2*)&Bs[cur][kk][n0 + 4];
            float av[8] = {a_lo.x, a_lo.y, a_lo.z, a_lo.w, a_hi.x, a_hi.y, a_hi.z, a_hi.w};
#pragma unroll
            for (int i = 0; i < 8; i++) {
                unsigned long long pd = dup2f(av[i]);
                acc[i][0] = ffma2(pd, b01.x, acc[i][0]);
                acc[i][1] = ffma2(pd, b01.y, acc[i][1]);
                acc[i][2] = ffma2(pd, b23.x, acc[i][2]);
                acc[i][3] = ffma2(pd, b23.y, acc[i][3]);
            }
        }
        if (kt < KDIM / 8 - 1) {
#pragma unroll
            for (int i = 0; i < 4; i++) As[nxt][ac4 + i][arow] = ((const float*)&aN)[i];
        }
        cp_wait0();
        __syncthreads();
    }

    // ---- epilogue ----
#pragma unroll
    for (int i = 0; i < 8; i++) {
        float2 p0 = unpack2(acc[i][0]);
        float2 p1 = unpack2(acc[i][1]);
        float2 p2 = unpack2(acc[i][2]);
        float2 p3 = unpack2(acc[i][3]);
        size_t off = (size_t)(m0g + m0 + i) * DDIM + n0g + n0;
        *(float4*)&g_Wh[off]     = make_float4(p0.x, p0.y, p1.x, p1.y);
        *(float4*)&g_Wh[off + 4] = make_float4(p2.x, p2.y, p3.x, p3.y);
    }
}

// =====================================================================
// Kernel 2: Wh1 = Wh @ a[0:256], Wh2 = Wh @ a[256:512]. One warp per row.
// =====================================================================
__global__ void __launch_bounds__(256) k_rowdots(const float* __restrict__ avec) {
    const int row  = blockIdx.x * 8 + (threadIdx.x >> 5);
    const int lane = threadIdx.x & 31;
    const float4* wr = (const float4*)&g_Wh[(size_t)row * DDIM];
    float4 v0 = wr[lane], v1 = wr[lane + 32];
    const float4* aa = (const float4*)avec;
    float4 u0 = aa[lane], u1 = aa[lane + 32], u2 = aa[lane + 64], u3 = aa[lane + 96];
    float s1 = v0.x * u0.x + v0.y * u0.y + v0.z * u0.z + v0.w * u0.w
             + v1.x * u1.x + v1.y * u1.y + v1.z * u1.z + v1.w * u1.w;
    float s2 = v0.x * u2.x + v0.y * u2.y + v0.z * u2.z + v0.w * u2.w
             + v1.x * u3.x + v1.y * u3.y + v1.z * u3.z + v1.w * u3.w;
#pragma unroll
    for (int o = 16; o; o >>= 1) {
        s1 += __shfl_xor_sync(0xffffffffu, s1, o);
        s2 += __shfl_xor_sync(0xffffffffu, s2, o);
    }
    if (lane == 0) { g_Wh1[row] = s1; g_Wh2[row] = s2; }
}

// =====================================================================
// Kernel 3: fused masked-softmax attention + PV + ELU.
// BM=64 rows per CTA, BN=64 column tile, 128 CTAs (1 wave), 256 threads.
// No max subtraction needed (bounded logits; masked terms are exactly 0,
// matching exp(-9e15 - max) == 0 in the reference).
// Double-buffered cp.async for adj / Wh / Wh2 tiles.
// =====================================================================
// dynamic smem layout (bytes):
//   WhS  [2][64][256] f32 : 0      .. 131072
//   AdjS [2][64][64]  i32 : 131072 .. 163840
//   Ps   [64][68]     f32 : 163840 .. 181248
//   Wh1S [64]         f32 : 181248 .. 181504
//   Wh2S [2][64]      f32 : 181504 .. 182016
//   LS   [64]         f32 : 182016 .. 182272
#define K2_SMEM 182272

__global__ void __launch_bounds__(256) k_attn(const int* __restrict__ adj,
                                              float* __restrict__ out) {
    extern __shared__ char smraw[];
    float* WhS  = (float*)smraw;
    int*   AdjS = (int*)(smraw + 131072);
    float* Ps   = (float*)(smraw + 163840);
    float* Wh1S = (float*)(smraw + 181248);
    float* Wh2S = (float*)(smraw + 181504);
    float* LS   = (float*)(smraw + 182016);

    const int t     = threadIdx.x;
    const int m0blk = blockIdx.x * 64;

    auto prefetch = [&](int jb, int nb) {
#pragma unroll
        for (int i = 0; i < 16; i++) {                  // Wh tile 64x256 f32
            int idx = t + i * 256;
            int row = idx >> 6, c4 = (idx & 63) << 2;
            cp16(&WhS[nb * 16384 + row * 256 + c4],
                 &g_Wh[((size_t)jb * 64 + row) * 256 + c4]);
        }
#pragma unroll
        for (int i = 0; i < 4; i++) {                   // adj tile 64x64 i32
            int idx = t + i * 256;
            int row = idx >> 4, c4 = (idx & 15) << 2;
            cp16(&AdjS[nb * 4096 + row * 64 + c4],
                 &adj[(size_t)(m0blk + row) * NROWS + jb * 64 + c4]);
        }
        if (t < 16)                                      // Wh2 tile 64 f32
            cp16(&Wh2S[nb * 64 + t * 4], &g_Wh2[jb * 64 + t * 4]);
    };

    // prologue
    prefetch(0, 0);
    cp_commit();
    if (t < 64) Wh1S[t] = g_Wh1[m0blk + t];
    cp_wait0();
    __syncthreads();

    float lp[16];
#pragma unroll
    for (int i = 0; i < 16; i++) lp[i] = 0.f;

    unsigned long long acc[8][4];
#pragma unroll
    for (int i = 0; i < 8; i++)
#pragma unroll
        for (int j = 0; j < 4; j++) acc[i][j] = 0ull;

    const int gA = t >> 6, laneA = t & 63;       // phase-A map (row-stable)
    const int m0 = (t >> 5) * 8, d0 = (t & 31) * 8;  // phase-B map

    for (int jb = 0; jb < NROWS / 64; ++jb) {
        const int cur = jb & 1, nxt = cur ^ 1;
        if (jb < NROWS / 64 - 1) { prefetch(jb + 1, nxt); cp_commit(); }

        // ---- phase A: p = adj ? exp(leaky(Wh1_i + Wh2_j)) : 0 ----
        {
            const int*   ad  = &AdjS[cur * 4096];
            const float  w2  = Wh2S[cur * 64 + laneA];
#pragma unroll
            for (int mm = 0; mm < 16; ++mm) {
                int   m = gA * 16 + mm;
                int   av = ad[m * 64 + laneA];
                float e  = Wh1S[m] + w2;
                e = fmaxf(e, 0.2f * e);                 // LeakyReLU(0.2)
                float p = (av > 0) ? __expf(e) : 0.f;
                lp[mm] += p;
                Ps[m * 68 + laneA] = p;
            }
        }
        __syncthreads();

        // ---- phase B: acc += P_tile @ Wh_tile (f32x2 packed FMA) ----
        {
            const float* whb = &WhS[cur * 16384];
#pragma unroll 1
            for (int j4 = 0; j4 < 16; ++j4) {
                float4 pv[8];
#pragma unroll
                for (int i = 0; i < 8; i++)
                    pv[i] = *(const float4*)&Ps[(m0 + i) * 68 + j4 * 4];
#pragma unroll
                for (int jj = 0; jj < 4; jj++) {
                    const float* wr = &whb[(j4 * 4 + jj) * 256 + d0];
                    ulonglong2 wA = *(const ulonglong2*)wr;
                    ulonglong2 wB = *(const ulonglong2*)(wr + 4);
#pragma unroll
                    for (int i = 0; i < 8; i++) {
                        float p = ((const float*)&pv[i])[jj];
                        unsigned long long pd = dup2f(p);
                        acc[i][0] = ffma2(pd, wA.x, acc[i][0]);
                        acc[i][1] = ffma2(pd, wA.y, acc[i][1]);
                        acc[i][2] = ffma2(pd, wB.x, acc[i][2]);
                        acc[i][3] = ffma2(pd, wB.y, acc[i][3]);
                    }
                }
            }
        }
        cp_wait0();
        __syncthreads();
    }

    // ---- row-sum reduction (reuse Ps) ----
#pragma unroll
    for (int mm = 0; mm < 16; ++mm) Ps[(gA * 16 + mm) * 68 + laneA] = lp[mm];
    __syncthreads();
    if (t < 64) {
        float s = 0.f;
#pragma unroll 8
        for (int j = 0; j < 64; ++j) s += Ps[t * 68 + j];
        LS[t] = 1.0f / s;
    }
    __syncthreads();

    // ---- epilogue: out = elu(acc / l) ----
#pragma unroll
    for (int i = 0; i < 8; i++) {
        int   m = m0 + i;
        float r = LS[m];
        float v[8];
#pragma unroll
        for (int dd = 0; dd < 4; dd++) {
            float2 u = unpack2(acc[i][dd]);
            v[2 * dd] = u.x; v[2 * dd + 1] = u.y;
        }
#pragma unroll
        for (int k = 0; k < 8; k++) {
            float x = v[k] * r;
            v[k] = (x > 0.f) ? x : expm1f(x);
        }
        size_t off = (size_t)(m0blk + m) * DDIM + d0;
        *(float4*)&out[off]     = make_float4(v[0], v[1], v[2], v[3]);
        *(float4*)&out[off + 4] = make_float4(v[4], v[5], v[6], v[7]);
    }
}

// =====================================================================
extern "C" void kernel_launch(void* const* d_in, const int* in_sizes, int n_in,
                              void* d_out, int out_size) {
    const float* input  = (const float*)d_in[0];   // [8192,512]
    const int*   adj    = (const int*)d_in[1];     // [8192,8192]
    const float* weight = (const float*)d_in[2];   // [512,256]
    const float* avec   = (const float*)d_in[3];   // [512,1]
    float* out = (float*)d_out;                    // [8192,256]

    cudaFuncSetAttribute((const void*)k_attn,
                         cudaFuncAttributeMaxDynamicSharedMemorySize, K2_SMEM);

    k_gemm_wh<<<dim3(2, 64), 256>>>(input, weight);
    k_rowdots<<<NROWS / 8, 256>>>(avec);
    k_attn<<<NROWS / 64, 256, K2_SMEM>>>(adj, out);
}

// round 8
// speedup vs baseline: 1.0003x; 1.0003x over previous
#include <cuda_runtime.h>
#include <math.h>

#define NROWS 8192
#define KDIM  512
#define DDIM  256

// ---------------- scratch (no cudaMalloc allowed) ----------------
__device__ float g_Wh[NROWS * DDIM];   // 8 MB
__device__ float g_Wh1[NROWS];
__device__ float g_Wh2[NROWS];

// ---------------- f32x2 packed-FMA helpers (Blackwell) ----------------
__device__ __forceinline__ unsigned long long dup2f(float x) {
    unsigned long long r;
    asm("mov.b64 %0, {%1, %1};" : "=l"(r) : "f"(x));
    return r;
}
__device__ __forceinline__ unsigned long long ffma2(unsigned long long a,
                                                    unsigned long long b,
                                                    unsigned long long c) {
    unsigned long long d;
    asm("fma.rn.f32x2 %0, %1, %2, %3;" : "=l"(d) : "l"(a), "l"(b), "l"(c));
    return d;
}
__device__ __forceinline__ float2 unpack2(unsigned long long v) {
    float x, y;
    asm("mov.b64 {%0, %1}, %2;" : "=f"(x), "=f"(y) : "l"(v));
    return make_float2(x, y);
}

// ---------------- cp.async helpers ----------------
__device__ __forceinline__ void cp16(void* s, const void* g) {
    unsigned sa = (unsigned)__cvta_generic_to_shared(s);
    asm volatile("cp.async.cg.shared.global [%0], [%1], 16;" :: "r"(sa), "l"(g));
}
__device__ __forceinline__ void cp_commit() { asm volatile("cp.async.commit_group;"); }
__device__ __forceinline__ void cp_wait0()  { asm volatile("cp.async.wait_group 0;" ::: "memory"); }

// =====================================================================
// Kernel 1: Wh = input[8192,512] @ weight[512,256]
// 128x128 block tile, 8x8 micro tile, f32x2 accumulators, double-buffered.
// grid (2, 64), 256 threads.
// =====================================================================
__global__ void __launch_bounds__(256) k_gemm_wh(const float* __restrict__ A,
                                                 const float* __restrict__ B) {
    __shared__ __align__(16) float As[2][8][132];   // transposed [k][m], padded
    __shared__ __align__(16) float Bs[2][8][128];

    const int t   = threadIdx.x;
    const int m0g = blockIdx.y * 128;
    const int n0g = blockIdx.x * 128;

    const int arow = t >> 1, ac4 = (t & 1) * 4;     // A tile: 128 rows x 8 cols
    const int brow = t >> 5, bc  = (t & 31) * 4;    // B tile: 8 rows x 128 cols

    // ---- prologue: tile 0 ----
    float4 aReg = *(const float4*)&A[(size_t)(m0g + arow) * KDIM + ac4];
    cp16(&Bs[0][brow][bc], &B[(size_t)brow * DDIM + n0g + bc]);
    cp_commit();
#pragma unroll
    for (int i = 0; i < 4; i++) As[0][ac4 + i][arow] = ((const float*)&aReg)[i];
    cp_wait0();
    __syncthreads();

    unsigned long long acc[8][4];
#pragma unroll
    for (int i = 0; i < 8; i++)
#pragma unroll
        for (int j = 0; j < 4; j++) acc[i][j] = 0ull;

    const int m0 = (t >> 4) * 8, n0 = (t & 15) * 8;

    for (int kt = 0; kt < KDIM / 8; ++kt) {
        const int cur = kt & 1, nxt = cur ^ 1;
        float4 aN;
        if (kt < KDIM / 8 - 1) {
            aN = *(const float4*)&A[(size_t)(m0g + arow) * KDIM + (kt + 1) * 8 + ac4];
            cp16(&Bs[nxt][brow][bc], &B[(size_t)((kt + 1) * 8 + brow) * DDIM + n0g + bc]);
            cp_commit();
        }
#pragma unroll
        for (int kk = 0; kk < 8; kk++) {
            float4 a_lo = *(const float4*)&As[cur][kk][m0];
            float4 a_hi = *(const float4*)&As[cur][kk][m0 + 4];
            ulonglong2 b01 = *(const ulonglong2*)&Bs[cur][kk][n0];
            ulonglong2 b23 = *(const ulonglong2*)&Bs[cur][kk][n0 + 4];
            float av[8] = {a_lo.x, a_lo.y, a_lo.z, a_lo.w, a_hi.x, a_hi.y, a_hi.z, a_hi.w};
#pragma unroll
            for (int i = 0; i < 8; i++) {
                unsigned long long pd = dup2f(av[i]);
                acc[i][0] = ffma2(pd, b01.x, acc[i][0]);
                acc[i][1] = ffma2(pd, b01.y, acc[i][1]);
                acc[i][2] = ffma2(pd, b23.x, acc[i][2]);
                acc[i][3] = ffma2(pd, b23.y, acc[i][3]);
            }
        }
        if (kt < KDIM / 8 - 1) {
#pragma unroll
            for (int i = 0; i < 4; i++) As[nxt][ac4 + i][arow] = ((const float*)&aN)[i];
        }
        cp_wait0();
        __syncthreads();
    }

    // ---- epilogue ----
#pragma unroll
    for (int i = 0; i < 8; i++) {
        float2 p0 = unpack2(acc[i][0]);
        float2 p1 = unpack2(acc[i][1]);
        float2 p2 = unpack2(acc[i][2]);
        float2 p3 = unpack2(acc[i][3]);
        size_t off = (size_t)(m0g + m0 + i) * DDIM + n0g + n0;
        *(float4*)&g_Wh[off]     = make_float4(p0.x, p0.y, p1.x, p1.y);
        *(float4*)&g_Wh[off + 4] = make_float4(p2.x, p2.y, p3.x, p3.y);
    }
}

// =====================================================================
// Kernel 2: Wh1 = Wh @ a[0:256], Wh2 = Wh @ a[256:512]. One warp per row.
// =====================================================================
__global__ void __launch_bounds__(256) k_rowdots(const float* __restrict__ avec) {
    const int row  = blockIdx.x * 8 + (threadIdx.x >> 5);
    const int lane = threadIdx.x & 31;
    const float4* wr = (const float4*)&g_Wh[(size_t)row * DDIM];
    float4 v0 = wr[lane], v1 = wr[lane + 32];
    const float4* aa = (const float4*)avec;
    float4 u0 = aa[lane], u1 = aa[lane + 32], u2 = aa[lane + 64], u3 = aa[lane + 96];
    float s1 = v0.x * u0.x + v0.y * u0.y + v0.z * u0.z + v0.w * u0.w
             + v1.x * u1.x + v1.y * u1.y + v1.z * u1.z + v1.w * u1.w;
    float s2 = v0.x * u2.x + v0.y * u2.y + v0.z * u2.z + v0.w * u2.w
             + v1.x * u3.x + v1.y * u3.y + v1.z * u3.z + v1.w * u3.w;
#pragma unroll
    for (int o = 16; o; o >>= 1) {
        s1 += __shfl_xor_sync(0xffffffffu, s1, o);
        s2 += __shfl_xor_sync(0xffffffffu, s2, o);
    }
    if (lane == 0) { g_Wh1[row] = s1; g_Wh2[row] = s2; }
}

// =====================================================================
// Kernel 3: fused masked-softmax attention + PV + ELU.
// BM=64 rows per CTA, BN=64 column tile, 128 CTAs (1 wave), 256 threads.
// No max subtraction needed (bounded logits; masked terms are exactly 0,
// matching exp(-9e15 - max) == 0 in the reference).
// Double-buffered cp.async for adj / Wh / Wh2 tiles.
// =====================================================================
// dynamic smem layout (bytes):
//   WhS  [2][64][256] f32 : 0      .. 131072
//   AdjS [2][64][64]  i32 : 131072 .. 163840
//   Ps   [64][68]     f32 : 163840 .. 181248
//   Wh1S [64]         f32 : 181248 .. 181504
//   Wh2S [2][64]      f32 : 181504 .. 182016
//   LS   [64]         f32 : 182016 .. 182272
#define K2_SMEM 182272

__global__ void __launch_bounds__(256) k_attn(const int* __restrict__ adj,
                                              float* __restrict__ out) {
    extern __shared__ char smraw[];
    float* WhS  = (float*)smraw;
    int*   AdjS = (int*)(smraw + 131072);
    float* Ps   = (float*)(smraw + 163840);
    float* Wh1S = (float*)(smraw + 181248);
    float* Wh2S = (float*)(smraw + 181504);
    float* LS   = (float*)(smraw + 182016);

    const int t     = threadIdx.x;
    const int m0blk = blockIdx.x * 64;

    auto prefetch = [&](int jb, int nb) {
#pragma unroll
        for (int i = 0; i < 16; i++) {                  // Wh tile 64x256 f32
            int idx = t + i * 256;
            int row = idx >> 6, c4 = (idx & 63) << 2;
            cp16(&WhS[nb * 16384 + row * 256 + c4],
                 &g_Wh[((size_t)jb * 64 + row) * 256 + c4]);
        }
#pragma unroll
        for (int i = 0; i < 4; i++) {                   // adj tile 64x64 i32
            int idx = t + i * 256;
            int row = idx >> 4, c4 = (idx & 15) << 2;
            cp16(&AdjS[nb * 4096 + row * 64 + c4],
                 &adj[(size_t)(m0blk + row) * NROWS + jb * 64 + c4]);
        }
        if (t < 16)                                      // Wh2 tile 64 f32
            cp16(&Wh2S[nb * 64 + t * 4], &g_Wh2[jb * 64 + t * 4]);
    };

    // prologue
    prefetch(0, 0);
    cp_commit();
    if (t < 64) Wh1S[t] = g_Wh1[m0blk + t];
    cp_wait0();
    __syncthreads();

    float lp[16];
#pragma unroll
    for (int i = 0; i < 16; i++) lp[i] = 0.f;

    unsigned long long acc[8][4];
#pragma unroll
    for (int i = 0; i < 8; i++)
#pragma unroll
        for (int j = 0; j < 4; j++) acc[i][j] = 0ull;

    const int gA = t >> 6, laneA = t & 63;       // phase-A map (row-stable)
    const int m0 = (t >> 5) * 8, d0 = (t & 31) * 8;  // phase-B map

    for (int jb = 0; jb < NROWS / 64; ++jb) {
        const int cur = jb & 1, nxt = cur ^ 1;
        if (jb < NROWS / 64 - 1) { prefetch(jb + 1, nxt); cp_commit(); }

        // ---- phase A: p = adj ? exp(leaky(Wh1_i + Wh2_j)) : 0 ----
        {
            const int*   ad  = &AdjS[cur * 4096];
            const float  w2  = Wh2S[cur * 64 + laneA];
#pragma unroll
            for (int mm = 0; mm < 16; ++mm) {
                int   m = gA * 16 + mm;
                int   av = ad[m * 64 + laneA];
                float e  = Wh1S[m] + w2;
                e = fmaxf(e, 0.2f * e);                 // LeakyReLU(0.2)
                float p = (av > 0) ? __expf(e) : 0.f;
                lp[mm] += p;
                Ps[m * 68 + laneA] = p;
            }
        }
        __syncthreads();

        // ---- phase B: acc += P_tile @ Wh_tile (f32x2 packed FMA) ----
        {
            const float* whb = &WhS[cur * 16384];
#pragma unroll 1
            for (int j4 = 0; j4 < 16; ++j4) {
                float4 pv[8];
#pragma unroll
                for (int i = 0; i < 8; i++)
                    pv[i] = *(const float4*)&Ps[(m0 + i) * 68 + j4 * 4];
#pragma unroll
                for (int jj = 0; jj < 4; jj++) {
                    const float* wr = &whb[(j4 * 4 + jj) * 256 + d0];
                    ulonglong2 wA = *(const ulonglong2*)wr;
                    ulonglong2 wB = *(const ulonglong2*)(wr + 4);
#pragma unroll
                    for (int i = 0; i < 8; i++) {
                        float p = ((const float*)&pv[i])[jj];
                        unsigned long long pd = dup2f(p);
                        acc[i][0] = ffma2(pd, wA.x, acc[i][0]);
                        acc[i][1] = ffma2(pd, wA.y, acc[i][1]);
                        acc[i][2] = ffma2(pd, wB.x, acc[i][2]);
                        acc[i][3] = ffma2(pd, wB.y, acc[i][3]);
                    }
                }
            }
        }
        cp_wait0();
        __syncthreads();
    }

    // ---- row-sum reduction (reuse Ps) ----
#pragma unroll
    for (int mm = 0; mm < 16; ++mm) Ps[(gA * 16 + mm) * 68 + laneA] = lp[mm];
    __syncthreads();
    if (t < 64) {
        float s = 0.f;
#pragma unroll 8
        for (int j = 0; j < 64; ++j) s += Ps[t * 68 + j];
        LS[t] = 1.0f / s;
    }
    __syncthreads();

    // ---- epilogue: out = elu(acc / l) ----
#pragma unroll
    for (int i = 0; i < 8; i++) {
        int   m = m0 + i;
        float r = LS[m];
        float v[8];
#pragma unroll
        for (int dd = 0; dd < 4; dd++) {
            float2 u = unpack2(acc[i][dd]);
            v[2 * dd] = u.x; v[2 * dd + 1] = u.y;
        }
#pragma unroll
        for (int k = 0; k < 8; k++) {
            float x = v[k] * r;
            v[k] = (x > 0.f) ? x : expm1f(x);
        }
        size_t off = (size_t)(m0blk + m) * DDIM + d0;
        *(float4*)&out[off]     = make_float4(v[0], v[1], v[2], v[3]);
        *(float4*)&out[off + 4] = make_float4(v[4], v[5], v[6], v[7]);
    }
}

// =====================================================================
extern "C" void kernel_launch(void* const* d_in, const int* in_sizes, int n_in,
                              void* d_out, int out_size) {
    const float* input  = (const float*)d_in[0];   // [8192,512]
    const int*   adj    = (const int*)d_in[1];     // [8192,8192]
    const float* weight = (const float*)d_in[2];   // [512,256]
    const float* avec   = (const float*)d_in[3];   // [512,1]
    float* out = (float*)d_out;                    // [8192,256]

    cudaFuncSetAttribute((const void*)k_attn,
                         cudaFuncAttributeMaxDynamicSharedMemorySize, K2_SMEM);

    k_gemm_wh<<<dim3(2, 64), 256>>>(input, weight);
    k_rowdots<<<NROWS / 8, 256>>>(avec);
    k_attn<<<NROWS / 64, 256, K2_SMEM>>>(adj, out);
}